// round 12
// baseline (speedup 1.0000x reference)
#include <cuda_runtime.h>
#include <cuda_fp16.h>
#include <math.h>
#include <stdint.h>

#define T_TOK 4096
#define DDIM  1024
#define NEXP  8
#define FDIM  512
#define FSDIM 1024
#define KDOWN 5120
#define TOPK  6

#define BK 64
#define MSTRIDE 144                 // A tile: 128 B data + 16 pad per m-row
#define ATILE (128 * MSTRIDE)       // 18432
#define BSTRIDE 272                 // B tile: 256 B data (128 n-halves) + 16 pad per k-row
#define BTILE (64 * BSTRIDE)        // 17408
#define IDXSTR 4096

// ---------------- scratch ----------------------------------------------------
__device__ float g_W[T_TOK * NEXP];
__device__ int   g_idx[NEXP * IDXSTR];    // selected tokens per expert
__device__ int   g_idxz[NEXP * IDXSTR];   // UNselected tokens per expert
__device__ int   g_cnt[NEXP];
__device__ int   g_cntz[NEXP];
__device__ __half g_X[T_TOK * DDIM];
// weights kept in ORIGINAL layout, just converted to fp16 ([k][n]-major)
__device__ __half g_Bg[NEXP * DDIM * FDIM];      // [e][d][f]
__device__ __half g_Bu[NEXP * DDIM * FDIM];
__device__ __half g_Bsg[DDIM * FSDIM];           // [d][f]
__device__ __half g_Bsu[DDIM * FSDIM];
__device__ __half g_Bd[KDOWN * DDIM];            // [e*F+f][d] then [4096+f][d]
__device__ __half g_H[(size_t)T_TOK * KDOWN];

// ---------------- helpers ----------------------------------------------------
__device__ __forceinline__ uint32_t smem_u32(const void* p) {
    uint32_t a;
    asm("{ .reg .u64 t; cvta.to.shared.u64 t, %1; cvt.u32.u64 %0, t; }"
        : "=r"(a) : "l"(p));
    return a;
}

#define CP16(dst, src) \
    asm volatile("cp.async.cg.shared.global [%0], [%1], 16;" :: "r"(dst), "l"(src) : "memory")
#define CP_COMMIT() asm volatile("cp.async.commit_group;" ::: "memory")
#define CP_WAIT1()  asm volatile("cp.async.wait_group 1;" ::: "memory")
#define CP_WAIT0()  asm volatile("cp.async.wait_group 0;" ::: "memory")

#define LDSM4(r0, r1, r2, r3, a) \
    asm volatile("ldmatrix.sync.aligned.m8n8.x4.shared.b16 {%0,%1,%2,%3}, [%4];" \
        : "=r"(r0), "=r"(r1), "=r"(r2), "=r"(r3) : "r"(a))

#define LDSM4T(r0, r1, r2, r3, a) \
    asm volatile("ldmatrix.sync.aligned.m8n8.x4.trans.shared.b16 {%0,%1,%2,%3}, [%4];" \
        : "=r"(r0), "=r"(r1), "=r"(r2), "=r"(r3) : "r"(a))

#define MMA16(d, a, b0, b1) \
    asm volatile( \
        "mma.sync.aligned.m16n8k16.row.col.f32.f16.f16.f32 " \
        "{%0,%1,%2,%3},{%4,%5,%6,%7},{%8,%9},{%0,%1,%2,%3};" \
        : "+f"((d)[0]), "+f"((d)[1]), "+f"((d)[2]), "+f"((d)[3]) \
        : "r"((a)[0]), "r"((a)[1]), "r"((a)[2]), "r"((a)[3]), "r"(b0), "r"(b1))

__device__ __forceinline__ uint32_t pk_h2(__half a, __half b) {
    __half2 t = __halves2half2(a, b);
    return *reinterpret_cast<uint32_t*>(&t);
}

// ---------------- counter reset ------------------------------------------------
__global__ void zcnt() {
    if (threadIdx.x < NEXP) { g_cnt[threadIdx.x] = 0; g_cntz[threadIdx.x] = 0; }
}

// ---------------- fused router: scores + topk lists + complement + X fp16 -------
__global__ void router_kernel(const float* __restrict__ x,
                              const float* __restrict__ rw,
                              __half* __restrict__ xh) {
    int gw = (blockIdx.x * blockDim.x + threadIdx.x) >> 5;
    int lane = threadIdx.x & 31;
    if (gw >= T_TOK) return;
    const float* xr = x + (size_t)gw * DDIM;
    __half* xo = xh + (size_t)gw * DDIM;
    float acc[NEXP];
#pragma unroll
    for (int e = 0; e < NEXP; e++) acc[e] = 0.f;
    for (int d = lane; d < DDIM; d += 32) {
        float xv = xr[d];
        xo[d] = __float2half_rn(xv);
        const float4* r4 = reinterpret_cast<const float4*>(rw + (size_t)d * NEXP);
        float4 r0 = r4[0], r1 = r4[1];
        acc[0] = fmaf(xv, r0.x, acc[0]); acc[1] = fmaf(xv, r0.y, acc[1]);
        acc[2] = fmaf(xv, r0.z, acc[2]); acc[3] = fmaf(xv, r0.w, acc[3]);
        acc[4] = fmaf(xv, r1.x, acc[4]); acc[5] = fmaf(xv, r1.y, acc[5]);
        acc[6] = fmaf(xv, r1.z, acc[6]); acc[7] = fmaf(xv, r1.w, acc[7]);
    }
#pragma unroll
    for (int off = 16; off > 0; off >>= 1)
#pragma unroll
        for (int e = 0; e < NEXP; e++)
            acc[e] += __shfl_xor_sync(0xffffffffu, acc[e], off);
    if (lane == 0) {
        float m = acc[0];
#pragma unroll
        for (int e = 1; e < NEXP; e++) m = fmaxf(m, acc[e]);
        float p[NEXP], s = 0.f;
#pragma unroll
        for (int e = 0; e < NEXP; e++) { p[e] = expf(acc[e] - m); s += p[e]; }
        float inv = 1.f / s;
#pragma unroll
        for (int e = 0; e < NEXP; e++) p[e] *= inv;
#pragma unroll
        for (int e = 0; e < NEXP; e++) {
            int rank = 0;
#pragma unroll
            for (int e2 = 0; e2 < NEXP; e2++)
                rank += (p[e2] > p[e] || (p[e2] == p[e] && e2 < e)) ? 1 : 0;
            bool sel = (rank < TOPK);
            g_W[gw * NEXP + e] = sel ? p[e] : 0.f;
            if (sel) {
                int pos = atomicAdd(&g_cnt[e], 1);
                g_idx[e * IDXSTR + pos] = gw;
            } else {
                int pos = atomicAdd(&g_cntz[e], 1);
                g_idxz[e * IDXSTR + pos] = gw;
            }
        }
    }
}

// ---------------- zero only unselected (token, expert) H slots -------------------
__global__ void zeroSel() {
    const int e = blockIdx.x;
    const int nz = g_cntz[e];
    const int sub = threadIdx.x >> 6;
    const int ln  = threadIdx.x & 63;
    for (int i = blockIdx.y * 4 + sub; i < nz; i += 32 * 4) {
        const int tok = g_idxz[e * IDXSTR + i];
        *reinterpret_cast<uint4*>(g_H + (size_t)tok * KDOWN + e * FDIM + ln * 8) =
            make_uint4(0, 0, 0, 0);
    }
}

// ---------------- flat streaming weight convert (NO transpose) -------------------
// seg 0: wg(4.19M) 1: wu 2: wd  (grid.x 4096)   3: wsg 4: wsu 5: wsd (1.05M, guard)
__global__ void cvtW(const float* __restrict__ wg, const float* __restrict__ wu,
                     const float* __restrict__ wd, const float* __restrict__ wsg,
                     const float* __restrict__ wsu, const float* __restrict__ wsd) {
    const int seg = blockIdx.y;
    const size_t i = ((size_t)blockIdx.x * 256 + threadIdx.x) * 4;
    const float* src;
    __half* dst;
    size_t n;
    switch (seg) {
        case 0: src = wg;  dst = g_Bg;  n = (size_t)NEXP * DDIM * FDIM; break;
        case 1: src = wu;  dst = g_Bu;  n = (size_t)NEXP * DDIM * FDIM; break;
        case 2: src = wd;  dst = g_Bd;  n = (size_t)NEXP * FDIM * DDIM; break;
        case 3: src = wsg; dst = g_Bsg; n = (size_t)DDIM * FSDIM; break;
        case 4: src = wsu; dst = g_Bsu; n = (size_t)DDIM * FSDIM; break;
        default: src = wsd; dst = g_Bd + (size_t)NEXP * FDIM * DDIM;
                 n = (size_t)FSDIM * DDIM; break;
    }
    if (i >= n) return;
    float4 v = *reinterpret_cast<const float4*>(src + i);
    uint2 p;
    p.x = pk_h2(__float2half_rn(v.x), __float2half_rn(v.y));
    p.y = pk_h2(__float2half_rn(v.z), __float2half_rn(v.w));
    *reinterpret_cast<uint2*>(dst + i) = p;
}

// ---------------- merged gate+up fp16 MMA GEMM (z=0..7 routed, z=8 shared) -------
// buffer: A[128m][64k] + Bg[64k][128n] + Bu[64k][128n]
#define GU_SBUF (ATILE + 2 * BTILE)   // 53248
#define GU_SMEM (2 * GU_SBUF)         // 106496

__global__ __launch_bounds__(256, 1)
void gu_mma(const __half* __restrict__ X,
            const __half* __restrict__ Gw,  const __half* __restrict__ Uw,
            const __half* __restrict__ Gsw, const __half* __restrict__ Usw) {
    const int e = blockIdx.z;
    const int bm = blockIdx.y * 128, bn = blockIdx.x * 128;

    const __half *Bg, *Bu;
    const int* tix = nullptr;
    int cnt = 0, colExp, scaled, rowlen;
    if (e < NEXP) {
        cnt = g_cnt[e];
        if (bm >= ((cnt + 127) & ~127)) return;
        if (bn >= FDIM) return;
        tix = g_idx + (size_t)e * IDXSTR;
        Bg = Gw + (size_t)e * DDIM * FDIM;   // [d][f]
        Bu = Uw + (size_t)e * DDIM * FDIM;
        colExp = e * FDIM; scaled = 1; rowlen = FDIM;
    } else {
        Bg = Gsw; Bu = Usw;
        colExp = NEXP * FDIM; scaled = 0; rowlen = FSDIM;
    }

    extern __shared__ __align__(16) char smem[];
    const uint32_t sb = smem_u32(smem);
    const int tid = threadIdx.x;
    const int wid = tid >> 5, lane = tid & 31;
    const int grp = lane >> 2, tI = lane & 3;
    const int wm = (wid >> 2) * 64, wn = (wid & 3) * 32;

    // A cp.async slots ([m][k], gathered rows)
    const int r0 = tid >> 3, q = tid & 7;
    uint32_t dsA[4];
    size_t gA[4];
#pragma unroll
    for (int p = 0; p < 4; p++) {
        const int row = r0 + 32 * p;
        dsA[p] = row * MSTRIDE + q * 16;
        const int tokA = tix ? tix[min(bm + row, cnt - 1)] : (bm + row);
        gA[p] = (size_t)tokA * DDIM + q * 8;
    }
    // B cp.async slots ([k][n], 64 rows x 256B)
    const int br = tid >> 2, bq = tid & 3;
    uint32_t dsB[4];
    size_t gBb[4];
#pragma unroll
    for (int p = 0; p < 4; p++) {
        dsB[p] = br * BSTRIDE + bq * 16 + p * 64;
        gBb[p] = (size_t)br * rowlen + bn + bq * 8 + p * 32;
    }

    const uint32_t aOff = (lane & 15) * MSTRIDE + (lane >> 4) * 16;
    const uint32_t bOff = (lane & 15) * BSTRIDE + (lane >> 4) * 16;  // trans-ldmatrix

    float accG[4][4][4], accU[4][4][4];
#pragma unroll
    for (int i = 0; i < 4; i++)
#pragma unroll
        for (int j = 0; j < 4; j++)
#pragma unroll
            for (int r = 0; r < 4; r++) { accG[i][j][r] = 0.f; accU[i][j][r] = 0.f; }

    const int NC = DDIM / BK;   // 16

    auto issue = [&](int kc, int buf) {
        const int k0 = kc * BK;
        const uint32_t s = sb + buf * GU_SBUF;
        const size_t bk = (size_t)k0 * rowlen;
#pragma unroll
        for (int p = 0; p < 4; p++) {
            CP16(s + dsA[p],                 X  + gA[p] + k0);
            CP16(s + ATILE + dsB[p],         Bg + gBb[p] + bk);
            CP16(s + ATILE + BTILE + dsB[p], Bu + gBb[p] + bk);
        }
        CP_COMMIT();
    };

    issue(0, 0);
    for (int kc = 0; kc < NC; kc++) {
        const int buf = kc & 1;
        if (kc + 1 < NC) { issue(kc + 1, buf ^ 1); CP_WAIT1(); }
        else             { CP_WAIT0(); }
        __syncthreads();
        const uint32_t s = sb + buf * GU_SBUF;
#pragma unroll
        for (int ks = 0; ks < 4; ks++) {
            uint32_t aF[4][4];
            const uint32_t aBase = s + wm * MSTRIDE + aOff + ks * 32;
#pragma unroll
            for (int tm = 0; tm < 4; tm++)
                LDSM4(aF[tm][0], aF[tm][1], aF[tm][2], aF[tm][3],
                      aBase + tm * 16 * MSTRIDE);
            const uint32_t bgB = s + ATILE + wn * 2 + bOff + ks * 16 * BSTRIDE;
            const uint32_t buB = bgB + BTILE;
#pragma unroll
            for (int tn2 = 0; tn2 < 2; tn2++) {
                uint32_t g[4], u[4];
                LDSM4T(g[0], g[1], g[2], g[3], bgB + tn2 * 32);
                LDSM4T(u[0], u[1], u[2], u[3], buB + tn2 * 32);
                const int tn = tn2 * 2;
#pragma unroll
                for (int tm = 0; tm < 4; tm++) MMA16(accG[tm][tn],     aF[tm], g[0], g[1]);
#pragma unroll
                for (int tm = 0; tm < 4; tm++) MMA16(accU[tm][tn],     aF[tm], u[0], u[1]);
#pragma unroll
                for (int tm = 0; tm < 4; tm++) MMA16(accG[tm][tn + 1], aF[tm], g[2], g[3]);
#pragma unroll
                for (int tm = 0; tm < 4; tm++) MMA16(accU[tm][tn + 1], aF[tm], u[2], u[3]);
            }
        }
        __syncthreads();
    }

    const int colbase = colExp + bn + wn;
#pragma unroll
    for (int tm = 0; tm < 4; tm++) {
#pragma unroll
        for (int half = 0; half < 2; half++) {
            const int i = bm + wm + tm * 16 + grp + half * 8;
            const int token = tix ? tix[min(i, cnt - 1)] : i;
            const float wgt = scaled ? g_W[token * NEXP + e] : 1.0f;
            const size_t rowoff = (size_t)token * KDOWN;
#pragma unroll
            for (int tn = 0; tn < 4; tn++) {
                float gv0 = accG[tm][tn][half * 2 + 0];
                float gv1 = accG[tm][tn][half * 2 + 1];
                float uv0 = accU[tm][tn][half * 2 + 0];
                float uv1 = accU[tm][tn][half * 2 + 1];
                float h0 = gv0 / (1.f + expf(-gv0)) * uv0 * wgt;
                float h1 = gv1 / (1.f + expf(-gv1)) * uv1 * wgt;
                const int col = colbase + tn * 8 + tI * 2;
                *reinterpret_cast<uint32_t*>(g_H + rowoff + col) =
                    pk_h2(__float2half_rn(h0), __float2half_rn(h1));
            }
        }
    }
}

// ---------------- down fp16 MMA GEMM (combine) --------------------------------------
// buffer: A(H)[128m][64k] + B(Bd)[64k][128n]
#define DN_SBUF (ATILE + BTILE)   // 35840
#define DN_SMEM (2 * DN_SBUF)     // 71680

__global__ __launch_bounds__(256, 2)
void dn_mma(float* __restrict__ out) {
    extern __shared__ __align__(16) char smem[];
    const uint32_t sb = smem_u32(smem);
    const int tid = threadIdx.x;
    const int wid = tid >> 5, lane = tid & 31;
    const int grp = lane >> 2, tI = lane & 3;
    const int wm = (wid >> 2) * 64, wn = (wid & 3) * 32;
    const int bm = blockIdx.y * 128, bn = blockIdx.x * 128;

    const int r0 = tid >> 3, q = tid & 7;
    uint32_t dsA[4];
    size_t gA[4];
#pragma unroll
    for (int p = 0; p < 4; p++) {
        const int row = r0 + 32 * p;
        dsA[p] = row * MSTRIDE + q * 16;
        gA[p] = (size_t)(bm + row) * KDOWN + q * 8;
    }
    const int br = tid >> 2, bq = tid & 3;
    uint32_t dsB[4];
    size_t gBb[4];
#pragma unroll
    for (int p = 0; p < 4; p++) {
        dsB[p] = br * BSTRIDE + bq * 16 + p * 64;
        gBb[p] = (size_t)br * DDIM + bn + bq * 8 + p * 32;
    }

    const uint32_t aOff = (lane & 15) * MSTRIDE + (lane >> 4) * 16;
    const uint32_t bOff = (lane & 15) * BSTRIDE + (lane >> 4) * 16;

    float acc[4][4][4];
#pragma unroll
    for (int i = 0; i < 4; i++)
#pragma unroll
        for (int j = 0; j < 4; j++)
#pragma unroll
            for (int r = 0; r < 4; r++) acc[i][j][r] = 0.f;

    const int NC = KDOWN / BK;   // 80

    auto issue = [&](int kc, int buf) {
        const int k0 = kc * BK;
        const uint32_t s = sb + buf * DN_SBUF;
        const size_t bk = (size_t)k0 * DDIM;
#pragma unroll
        for (int p = 0; p < 4; p++) {
            CP16(s + dsA[p],         g_H  + gA[p] + k0);
            CP16(s + ATILE + dsB[p], g_Bd + gBb[p] + bk);
        }
        CP_COMMIT();
    };

    issue(0, 0);
    for (int kc = 0; kc < NC; kc++) {
        const int buf = kc & 1;
        if (kc + 1 < NC) { issue(kc + 1, buf ^ 1); CP_WAIT1(); }
        else             { CP_WAIT0(); }
        __syncthreads();
        const uint32_t s = sb + buf * DN_SBUF;
#pragma unroll
        for (int ks = 0; ks < 4; ks++) {
            uint32_t aF[4][4];
            const uint32_t aBase = s + wm * MSTRIDE + aOff + ks * 32;
#pragma unroll
            for (int tm = 0; tm < 4; tm++)
                LDSM4(aF[tm][0], aF[tm][1], aF[tm][2], aF[tm][3],
                      aBase + tm * 16 * MSTRIDE);
            const uint32_t bB = s + ATILE + wn * 2 + bOff + ks * 16 * BSTRIDE;
#pragma unroll
            for (int tn2 = 0; tn2 < 2; tn2++) {
                uint32_t b[4];
                LDSM4T(b[0], b[1], b[2], b[3], bB + tn2 * 32);
                const int tn = tn2 * 2;
#pragma unroll
                for (int tm = 0; tm < 4; tm++) MMA16(acc[tm][tn],     aF[tm], b[0], b[1]);
#pragma unroll
                for (int tm = 0; tm < 4; tm++) MMA16(acc[tm][tn + 1], aF[tm], b[2], b[3]);
            }
        }
        __syncthreads();
    }

#pragma unroll
    for (int tm = 0; tm < 4; tm++) {
#pragma unroll
        for (int half = 0; half < 2; half++) {
            const int token = bm + wm + tm * 16 + grp + half * 8;
#pragma unroll
            for (int tn = 0; tn < 4; tn++) {
                const int col = bn + wn + tn * 8 + tI * 2;
                float2 v = make_float2(acc[tm][tn][half * 2], acc[tm][tn][half * 2 + 1]);
                *reinterpret_cast<float2*>(out + (size_t)token * DDIM + col) = v;
            }
        }
    }
}

// ---------------- launch ------------------------------------------------------------
extern "C" void kernel_launch(void* const* d_in, const int* in_sizes, int n_in,
                              void* d_out, int out_size) {
    const float* x   = (const float*)d_in[0];
    const float* rw  = (const float*)d_in[1];
    const float* wg  = (const float*)d_in[2];
    const float* wu  = (const float*)d_in[3];
    const float* wd  = (const float*)d_in[4];
    const float* wsg = (const float*)d_in[5];
    const float* wsu = (const float*)d_in[6];
    const float* wsd = (const float*)d_in[7];
    float* out = (float*)d_out;

    void *pX, *pBg, *pBu, *pBsg, *pBsu;
    cudaGetSymbolAddress(&pX, g_X);
    cudaGetSymbolAddress(&pBg, g_Bg);   cudaGetSymbolAddress(&pBu, g_Bu);
    cudaGetSymbolAddress(&pBsg, g_Bsg); cudaGetSymbolAddress(&pBsu, g_Bsu);

    cudaFuncSetAttribute(gu_mma, cudaFuncAttributeMaxDynamicSharedMemorySize, GU_SMEM);
    cudaFuncSetAttribute(dn_mma, cudaFuncAttributeMaxDynamicSharedMemorySize, DN_SMEM);

    // 1: reset counters
    zcnt<<<1, 32>>>();
    // 2: fused router (scores + topk + complement lists + X fp16)
    router_kernel<<<T_TOK / 4, 128>>>(x, rw, (__half*)pX);
    // 3: zero only unselected (token, expert) H slots
    zeroSel<<<dim3(NEXP, 32), 256>>>();
    // 4: flat streaming weight convert (replaces both transpose kernels)
    cvtW<<<dim3(4096, 6), 256>>>(wg, wu, wd, wsg, wsu, wsd);
    // 5: merged gate+up (routed z=0..7 gathered, shared z=8 dense)
    gu_mma<<<dim3(FSDIM / 128, T_TOK / 128, NEXP + 1), 256, GU_SMEM>>>(
        (const __half*)pX,
        (const __half*)pBg,  (const __half*)pBu,
        (const __half*)pBsg, (const __half*)pBsu);
    // 6: down + weighted combine + shared add
    dn_mma<<<dim3(DDIM / 128, T_TOK / 128), 256, DN_SMEM>>>(out);
}

// round 13
// speedup vs baseline: 1.0449x; 1.0449x over previous
#include <cuda_runtime.h>
#include <cuda_fp16.h>
#include <math.h>
#include <stdint.h>

#define T_TOK 4096
#define DDIM  1024
#define NEXP  8
#define FDIM  512
#define FSDIM 1024
#define KDOWN 5120
#define TOPK  6

#define BK 64
#define MSTRIDE 144                // 128 data + 16 pad: 16B-aligned, ldmatrix conflict-free
#define TILEB (128 * MSTRIDE)      // 18432 bytes per 128-row tile
#define IDXSTR 4096

// ---------------- scratch ----------------------------------------------------
__device__ float g_W[T_TOK * NEXP];
__device__ int   g_idx[NEXP * IDXSTR];    // selected tokens per expert
__device__ int   g_idxz[NEXP * IDXSTR];   // UNselected tokens per expert
__device__ int   g_cnt[NEXP];
__device__ int   g_cntz[NEXP];
__device__ __half g_X[T_TOK * DDIM];
__device__ __half g_Bg[NEXP * FDIM * DDIM];      // fp16 weights, K-major [n][k]
__device__ __half g_Bu[NEXP * FDIM * DDIM];
__device__ __half g_Bsg[FSDIM * DDIM];
__device__ __half g_Bsu[FSDIM * DDIM];
__device__ __half g_Bd[DDIM * KDOWN];            // [n=1024][k=5120]
__device__ __half g_H[(size_t)T_TOK * KDOWN];

// ---------------- helpers ----------------------------------------------------
__device__ __forceinline__ uint32_t smem_u32(const void* p) {
    uint32_t a;
    asm("{ .reg .u64 t; cvta.to.shared.u64 t, %1; cvt.u32.u64 %0, t; }"
        : "=r"(a) : "l"(p));
    return a;
}

#define CP16(dst, src) \
    asm volatile("cp.async.cg.shared.global [%0], [%1], 16;" :: "r"(dst), "l"(src) : "memory")
#define CP_COMMIT() asm volatile("cp.async.commit_group;" ::: "memory")
#define CP_WAIT1()  asm volatile("cp.async.wait_group 1;" ::: "memory")
#define CP_WAIT0()  asm volatile("cp.async.wait_group 0;" ::: "memory")

#define LDSM4(r0, r1, r2, r3, a) \
    asm volatile("ldmatrix.sync.aligned.m8n8.x4.shared.b16 {%0,%1,%2,%3}, [%4];" \
        : "=r"(r0), "=r"(r1), "=r"(r2), "=r"(r3) : "r"(a))

#define MMA16(d, a, b0, b1) \
    asm volatile( \
        "mma.sync.aligned.m16n8k16.row.col.f32.f16.f16.f32 " \
        "{%0,%1,%2,%3},{%4,%5,%6,%7},{%8,%9},{%0,%1,%2,%3};" \
        : "+f"((d)[0]), "+f"((d)[1]), "+f"((d)[2]), "+f"((d)[3]) \
        : "r"((a)[0]), "r"((a)[1]), "r"((a)[2]), "r"((a)[3]), "r"(b0), "r"(b1))

__device__ __forceinline__ uint32_t pk_h2(__half a, __half b) {
    __half2 t = __halves2half2(a, b);
    return *reinterpret_cast<uint32_t*>(&t);
}

// ---------------- fused router: scores + topk lists + complement + X fp16 -------
__global__ void router_kernel(const float* __restrict__ x,
                              const float* __restrict__ rw,
                              __half* __restrict__ xh) {
    int gw = (blockIdx.x * blockDim.x + threadIdx.x) >> 5;
    int lane = threadIdx.x & 31;
    if (gw >= T_TOK) return;
    const float* xr = x + (size_t)gw * DDIM;
    __half* xo = xh + (size_t)gw * DDIM;
    float acc[NEXP];
#pragma unroll
    for (int e = 0; e < NEXP; e++) acc[e] = 0.f;
    for (int d = lane; d < DDIM; d += 32) {
        float xv = xr[d];
        xo[d] = __float2half_rn(xv);
        const float4* r4 = reinterpret_cast<const float4*>(rw + (size_t)d * NEXP);
        float4 r0 = r4[0], r1 = r4[1];
        acc[0] = fmaf(xv, r0.x, acc[0]); acc[1] = fmaf(xv, r0.y, acc[1]);
        acc[2] = fmaf(xv, r0.z, acc[2]); acc[3] = fmaf(xv, r0.w, acc[3]);
        acc[4] = fmaf(xv, r1.x, acc[4]); acc[5] = fmaf(xv, r1.y, acc[5]);
        acc[6] = fmaf(xv, r1.z, acc[6]); acc[7] = fmaf(xv, r1.w, acc[7]);
    }
#pragma unroll
    for (int off = 16; off > 0; off >>= 1)
#pragma unroll
        for (int e = 0; e < NEXP; e++)
            acc[e] += __shfl_xor_sync(0xffffffffu, acc[e], off);
    if (lane == 0) {
        float m = acc[0];
#pragma unroll
        for (int e = 1; e < NEXP; e++) m = fmaxf(m, acc[e]);
        float p[NEXP], s = 0.f;
#pragma unroll
        for (int e = 0; e < NEXP; e++) { p[e] = expf(acc[e] - m); s += p[e]; }
        float inv = 1.f / s;
#pragma unroll
        for (int e = 0; e < NEXP; e++) p[e] *= inv;
#pragma unroll
        for (int e = 0; e < NEXP; e++) {
            int rank = 0;
#pragma unroll
            for (int e2 = 0; e2 < NEXP; e2++)
                rank += (p[e2] > p[e] || (p[e2] == p[e] && e2 < e)) ? 1 : 0;
            bool sel = (rank < TOPK);
            g_W[gw * NEXP + e] = sel ? p[e] : 0.f;
            if (sel) {
                int pos = atomicAdd(&g_cnt[e], 1);
                g_idx[e * IDXSTR + pos] = gw;
            } else {
                int pos = atomicAdd(&g_cntz[e], 1);
                g_idxz[e * IDXSTR + pos] = gw;
            }
        }
    }
}

// ---------------- zero only unselected (token, expert) H slots -------------------
__global__ void zeroSel() {
    const int e = blockIdx.x;
    const int nz = g_cntz[e];
    const int sub = threadIdx.x >> 6;
    const int ln  = threadIdx.x & 63;
    for (int i = blockIdx.y * 4 + sub; i < nz; i += 32 * 4) {
        const int tok = g_idxz[e * IDXSTR + i];
        *reinterpret_cast<uint4*>(g_H + (size_t)tok * KDOWN + e * FDIM + ln * 8) =
            make_uint4(0, 0, 0, 0);
    }
}

// ---------------- merged weight transpose/convert + counter reset ----------------
__device__ __forceinline__ void tpose_body(
    const float* __restrict__ src, __half* __restrict__ dst,
    int C, long long zs, long long zd, int rs) {
    __shared__ float t[32][33];
    int c0 = blockIdx.x * 32, r0 = blockIdx.y * 32;
    int tx = threadIdx.x, ty = threadIdx.y;
#pragma unroll
    for (int k = 0; k < 32; k += 8)
        t[ty + k][tx] = src[zs + (long long)(r0 + ty + k) * C + c0 + tx];
    __syncthreads();
#pragma unroll
    for (int k = 0; k < 32; k += 8) {
        float v = t[tx][ty + k];
        int n = c0 + ty + k, r = r0 + tx;
        dst[zd + (long long)n * rs + r] = __float2half_rn(v);
    }
}

// z 0..7: w_gate e | z 8..15: w_up e | z 16: ws_gate | z 17: ws_up
// z 18..25: w_down e (y<16) | z 26: ws_down.  grid(32, 32, 27), block(32, 8)
__global__ void prepAll(const float* __restrict__ wg, const float* __restrict__ wu,
                        const float* __restrict__ wsg, const float* __restrict__ wsu,
                        const float* __restrict__ wd,  const float* __restrict__ wsd,
                        __half* bg, __half* bu, __half* bsg, __half* bsu, __half* bd) {
    // embedded counter reset (completes before router launches)
    if (blockIdx.x == 0 && blockIdx.y == 0 && blockIdx.z == 0 &&
        threadIdx.y == 0 && threadIdx.x < NEXP) {
        g_cnt[threadIdx.x] = 0;
        g_cntz[threadIdx.x] = 0;
    }
    int z = blockIdx.z;
    if (z < 8) {
        if (blockIdx.x >= 16) return;     // w_gate cols = FDIM
        tpose_body(wg, bg, FDIM, (long long)z * DDIM * FDIM, (long long)z * FDIM * DDIM, DDIM);
    } else if (z < 16) {
        if (blockIdx.x >= 16) return;
        int e = z - 8;
        tpose_body(wu, bu, FDIM, (long long)e * DDIM * FDIM, (long long)e * FDIM * DDIM, DDIM);
    } else if (z == 16) {
        tpose_body(wsg, bsg, FSDIM, 0, 0, DDIM);
    } else if (z == 17) {
        tpose_body(wsu, bsu, FSDIM, 0, 0, DDIM);
    } else if (z < 26) {
        if (blockIdx.y >= 16) return;     // w_down rows = FDIM
        int e = z - 18;
        tpose_body(wd, bd, DDIM, (long long)e * FDIM * DDIM, (long long)e * FDIM, KDOWN);
    } else {
        tpose_body(wsd, bd, DDIM, 0, (long long)NEXP * FDIM, KDOWN);
    }
}

// ---------------- merged gate+up fp16 MMA GEMM (z=0..7 routed, z=8 shared) -------
#define GU_SBUF (3 * TILEB)       // 55296
#define GU_SMEM (2 * GU_SBUF)     // 110592

__global__ __launch_bounds__(256, 1)
void gu_mma(const __half* __restrict__ X,
            const __half* __restrict__ Gw,  const __half* __restrict__ Uw,
            const __half* __restrict__ Gsw, const __half* __restrict__ Usw) {
    const int e = blockIdx.z;
    const int bm = blockIdx.y * 128, bn = blockIdx.x * 128;

    const __half *Bg, *Bu;
    const int* tix = nullptr;
    int cnt = 0, colExp, scaled;
    if (e < NEXP) {
        cnt = g_cnt[e];
        if (bm >= ((cnt + 127) & ~127)) return;
        if (bn >= FDIM) return;
        tix = g_idx + (size_t)e * IDXSTR;
        Bg = Gw + (size_t)e * FDIM * DDIM;
        Bu = Uw + (size_t)e * FDIM * DDIM;
        colExp = e * FDIM; scaled = 1;
    } else {
        Bg = Gsw; Bu = Usw;
        colExp = NEXP * FDIM; scaled = 0;
    }

    extern __shared__ __align__(16) char smem[];
    const uint32_t sb = smem_u32(smem);
    const int tid = threadIdx.x;
    const int wid = tid >> 5, lane = tid & 31;
    const int grp = lane >> 2, tI = lane & 3;
    const int wm = (wid >> 2) * 64, wn = (wid & 3) * 32;

    const int r0 = tid >> 3, q = tid & 7;
    uint32_t ds[4];
    size_t gA[4], gB[4];
#pragma unroll
    for (int p = 0; p < 4; p++) {
        const int row = r0 + 32 * p;
        ds[p] = row * MSTRIDE + q * 16;
        const int tokA = tix ? tix[min(bm + row, cnt - 1)] : (bm + row);
        gA[p] = (size_t)tokA * DDIM + q * 8;
        gB[p] = (size_t)(bn + row) * DDIM + q * 8;
    }

    const uint32_t aOff = (lane & 15) * MSTRIDE + (lane >> 4) * 16;
    const uint32_t bOff = (lane & 7) * MSTRIDE + ((lane >> 3) & 1) * 16
                        + (lane >> 4) * 8 * MSTRIDE;

    float accG[4][4][4], accU[4][4][4];
#pragma unroll
    for (int i = 0; i < 4; i++)
#pragma unroll
        for (int j = 0; j < 4; j++)
#pragma unroll
            for (int r = 0; r < 4; r++) { accG[i][j][r] = 0.f; accU[i][j][r] = 0.f; }

    const int NC = DDIM / BK;   // 16

    auto issue = [&](int kc, int buf) {
        const int k0 = kc * BK;
        const uint32_t s = sb + buf * GU_SBUF;
#pragma unroll
        for (int p = 0; p < 4; p++) {
            CP16(s + ds[p],             X  + gA[p] + k0);
            CP16(s + TILEB + ds[p],     Bg + gB[p] + k0);
            CP16(s + 2 * TILEB + ds[p], Bu + gB[p] + k0);
        }
        CP_COMMIT();
    };

    issue(0, 0);
    for (int kc = 0; kc < NC; kc++) {
        const int buf = kc & 1;
        if (kc + 1 < NC) { issue(kc + 1, buf ^ 1); CP_WAIT1(); }
        else             { CP_WAIT0(); }
        __syncthreads();
        const uint32_t s = sb + buf * GU_SBUF;
#pragma unroll
        for (int ks = 0; ks < 4; ks++) {
            uint32_t aF[4][4];
            const uint32_t aBase = s + wm * MSTRIDE + aOff + ks * 32;
#pragma unroll
            for (int tm = 0; tm < 4; tm++)
                LDSM4(aF[tm][0], aF[tm][1], aF[tm][2], aF[tm][3],
                      aBase + tm * 16 * MSTRIDE);
            const uint32_t bgB = s + TILEB + wn * MSTRIDE + bOff + ks * 32;
            const uint32_t buB = s + 2 * TILEB + wn * MSTRIDE + bOff + ks * 32;
#pragma unroll
            for (int tn2 = 0; tn2 < 2; tn2++) {
                uint32_t g[4], u[4];
                LDSM4(g[0], g[1], g[2], g[3], bgB + tn2 * 16 * MSTRIDE);
                LDSM4(u[0], u[1], u[2], u[3], buB + tn2 * 16 * MSTRIDE);
                const int tn = tn2 * 2;
#pragma unroll
                for (int tm = 0; tm < 4; tm++) MMA16(accG[tm][tn],     aF[tm], g[0], g[1]);
#pragma unroll
                for (int tm = 0; tm < 4; tm++) MMA16(accU[tm][tn],     aF[tm], u[0], u[1]);
#pragma unroll
                for (int tm = 0; tm < 4; tm++) MMA16(accG[tm][tn + 1], aF[tm], g[2], g[3]);
#pragma unroll
                for (int tm = 0; tm < 4; tm++) MMA16(accU[tm][tn + 1], aF[tm], u[2], u[3]);
            }
        }
        __syncthreads();
    }

    const int colbase = colExp + bn + wn;
#pragma unroll
    for (int tm = 0; tm < 4; tm++) {
#pragma unroll
        for (int half = 0; half < 2; half++) {
            const int i = bm + wm + tm * 16 + grp + half * 8;
            const int token = tix ? tix[min(i, cnt - 1)] : i;
            const float wgt = scaled ? g_W[token * NEXP + e] : 1.0f;
            const size_t rowoff = (size_t)token * KDOWN;
#pragma unroll
            for (int tn = 0; tn < 4; tn++) {
                float gv0 = accG[tm][tn][half * 2 + 0];
                float gv1 = accG[tm][tn][half * 2 + 1];
                float uv0 = accU[tm][tn][half * 2 + 0];
                float uv1 = accU[tm][tn][half * 2 + 1];
                float h0 = gv0 / (1.f + expf(-gv0)) * uv0 * wgt;
                float h1 = gv1 / (1.f + expf(-gv1)) * uv1 * wgt;
                const int col = colbase + tn * 8 + tI * 2;
                *reinterpret_cast<uint32_t*>(g_H + rowoff + col) =
                    pk_h2(__float2half_rn(h0), __float2half_rn(h1));
            }
        }
    }
}

// ---------------- down fp16 MMA GEMM (combine) --------------------------------------
#define DN_SBUF (2 * TILEB)       // 36864
#define DN_SMEM (2 * DN_SBUF)     // 73728

__global__ __launch_bounds__(256, 2)
void dn_mma(float* __restrict__ out) {
    extern __shared__ __align__(16) char smem[];
    const uint32_t sb = smem_u32(smem);
    const int tid = threadIdx.x;
    const int wid = tid >> 5, lane = tid & 31;
    const int grp = lane >> 2, tI = lane & 3;
    const int wm = (wid >> 2) * 64, wn = (wid & 3) * 32;
    const int bm = blockIdx.y * 128, bn = blockIdx.x * 128;

    const int r0 = tid >> 3, q = tid & 7;
    uint32_t ds[4];
    size_t gA[4], gB[4];
#pragma unroll
    for (int p = 0; p < 4; p++) {
        const int row = r0 + 32 * p;
        ds[p] = row * MSTRIDE + q * 16;
        gA[p] = (size_t)(bm + row) * KDOWN + q * 8;
        gB[p] = (size_t)(bn + row) * KDOWN + q * 8;
    }

    const uint32_t aOff = (lane & 15) * MSTRIDE + (lane >> 4) * 16;
    const uint32_t bOff = (lane & 7) * MSTRIDE + ((lane >> 3) & 1) * 16
                        + (lane >> 4) * 8 * MSTRIDE;

    float acc[4][4][4];
#pragma unroll
    for (int i = 0; i < 4; i++)
#pragma unroll
        for (int j = 0; j < 4; j++)
#pragma unroll
            for (int r = 0; r < 4; r++) acc[i][j][r] = 0.f;

    const int NC = KDOWN / BK;   // 80

    auto issue = [&](int kc, int buf) {
        const int k0 = kc * BK;
        const uint32_t s = sb + buf * DN_SBUF;
#pragma unroll
        for (int p = 0; p < 4; p++) {
            CP16(s + ds[p],         g_H  + gA[p] + k0);
            CP16(s + TILEB + ds[p], g_Bd + gB[p] + k0);
        }
        CP_COMMIT();
    };

    issue(0, 0);
    for (int kc = 0; kc < NC; kc++) {
        const int buf = kc & 1;
        if (kc + 1 < NC) { issue(kc + 1, buf ^ 1); CP_WAIT1(); }
        else             { CP_WAIT0(); }
        __syncthreads();
        const uint32_t s = sb + buf * DN_SBUF;
#pragma unroll
        for (int ks = 0; ks < 4; ks++) {
            uint32_t aF[4][4];
            const uint32_t aBase = s + wm * MSTRIDE + aOff + ks * 32;
#pragma unroll
            for (int tm = 0; tm < 4; tm++)
                LDSM4(aF[tm][0], aF[tm][1], aF[tm][2], aF[tm][3],
                      aBase + tm * 16 * MSTRIDE);
            const uint32_t bB = s + TILEB + wn * MSTRIDE + bOff + ks * 32;
#pragma unroll
            for (int tn2 = 0; tn2 < 2; tn2++) {
                uint32_t b[4];
                LDSM4(b[0], b[1], b[2], b[3], bB + tn2 * 16 * MSTRIDE);
                const int tn = tn2 * 2;
#pragma unroll
                for (int tm = 0; tm < 4; tm++) MMA16(acc[tm][tn],     aF[tm], b[0], b[1]);
#pragma unroll
                for (int tm = 0; tm < 4; tm++) MMA16(acc[tm][tn + 1], aF[tm], b[2], b[3]);
            }
        }
        __syncthreads();
    }

#pragma unroll
    for (int tm = 0; tm < 4; tm++) {
#pragma unroll
        for (int half = 0; half < 2; half++) {
            const int token = bm + wm + tm * 16 + grp + half * 8;
#pragma unroll
            for (int tn = 0; tn < 4; tn++) {
                const int col = bn + wn + tn * 8 + tI * 2;
                float2 v = make_float2(acc[tm][tn][half * 2], acc[tm][tn][half * 2 + 1]);
                *reinterpret_cast<float2*>(out + (size_t)token * DDIM + col) = v;
            }
        }
    }
}

// ---------------- launch ------------------------------------------------------------
extern "C" void kernel_launch(void* const* d_in, const int* in_sizes, int n_in,
                              void* d_out, int out_size) {
    const float* x   = (const float*)d_in[0];
    const float* rw  = (const float*)d_in[1];
    const float* wg  = (const float*)d_in[2];
    const float* wu  = (const float*)d_in[3];
    const float* wd  = (const float*)d_in[4];
    const float* wsg = (const float*)d_in[5];
    const float* wsu = (const float*)d_in[6];
    const float* wsd = (const float*)d_in[7];
    float* out = (float*)d_out;

    void *pX, *pBg, *pBu, *pBsg, *pBsu;
    cudaGetSymbolAddress(&pX, g_X);
    cudaGetSymbolAddress(&pBg, g_Bg);   cudaGetSymbolAddress(&pBu, g_Bu);
    cudaGetSymbolAddress(&pBsg, g_Bsg); cudaGetSymbolAddress(&pBsu, g_Bsu);
    void* pBd;
    cudaGetSymbolAddress(&pBd, g_Bd);

    cudaFuncSetAttribute(gu_mma, cudaFuncAttributeMaxDynamicSharedMemorySize, GU_SMEM);
    cudaFuncSetAttribute(dn_mma, cudaFuncAttributeMaxDynamicSharedMemorySize, DN_SMEM);

    // 1: merged weight transpose/convert + embedded counter reset
    dim3 tb(32, 8);
    prepAll<<<dim3(32, 32, 27), tb>>>(wg, wu, wsg, wsu, wd, wsd,
        (__half*)pBg, (__half*)pBu, (__half*)pBsg, (__half*)pBsu, (__half*)pBd);
    // 2: fused router (scores + topk + complement lists + X fp16)
    router_kernel<<<T_TOK / 4, 128>>>(x, rw, (__half*)pX);
    // 3: zero only unselected (token, expert) H slots
    zeroSel<<<dim3(NEXP, 32), 256>>>();
    // 4: merged gate+up (routed z=0..7 gathered, shared z=8 dense)
    gu_mma<<<dim3(FSDIM / 128, T_TOK / 128, NEXP + 1), 256, GU_SMEM>>>(
        (const __half*)pX,
        (const __half*)pBg,  (const __half*)pBu,
        (const __half*)pBsg, (const __half*)pBsu);
    // 5: down + weighted combine + shared add
    dn_mma<<<dim3(DDIM / 128, T_TOK / 128), 256, DN_SMEM>>>(out);
}

// round 14
// speedup vs baseline: 1.0886x; 1.0418x over previous
#include <cuda_runtime.h>
#include <cuda_fp16.h>
#include <math.h>
#include <stdint.h>

#define T_TOK 4096
#define DDIM  1024
#define NEXP  8
#define FDIM  512
#define FSDIM 1024
#define KDOWN 5120
#define TOPK  6

#define BK 64
#define MSTRIDE 144                // 128 data + 16 pad: 16B-aligned, ldmatrix conflict-free
#define TILEB (128 * MSTRIDE)      // 18432 bytes per 128-row tile
#define BTILE64 (64 * MSTRIDE)     // 9216 bytes per 64-row tile
#define IDXSTR 4096

// ---------------- scratch ----------------------------------------------------
__device__ float g_W[T_TOK * NEXP];
__device__ int   g_idx[NEXP * IDXSTR];
__device__ int   g_idxz[NEXP * IDXSTR];
__device__ int   g_cnt[NEXP];
__device__ int   g_cntz[NEXP];
__device__ __half g_X[T_TOK * DDIM];
__device__ __half g_Bg[NEXP * FDIM * DDIM];      // fp16 weights, K-major [n][k]
__device__ __half g_Bu[NEXP * FDIM * DDIM];
__device__ __half g_Bsg[FSDIM * DDIM];
__device__ __half g_Bsu[FSDIM * DDIM];
__device__ __half g_Bd[DDIM * KDOWN];            // [n=1024][k=5120]
__device__ __half g_H[(size_t)T_TOK * KDOWN];

// ---------------- helpers ----------------------------------------------------
__device__ __forceinline__ uint32_t smem_u32(const void* p) {
    uint32_t a;
    asm("{ .reg .u64 t; cvta.to.shared.u64 t, %1; cvt.u32.u64 %0, t; }"
        : "=r"(a) : "l"(p));
    return a;
}

#define CP16(dst, src) \
    asm volatile("cp.async.cg.shared.global [%0], [%1], 16;" :: "r"(dst), "l"(src) : "memory")
#define CP_COMMIT() asm volatile("cp.async.commit_group;" ::: "memory")
#define CP_WAIT1()  asm volatile("cp.async.wait_group 1;" ::: "memory")
#define CP_WAIT0()  asm volatile("cp.async.wait_group 0;" ::: "memory")

#define LDSM4(r0, r1, r2, r3, a) \
    asm volatile("ldmatrix.sync.aligned.m8n8.x4.shared.b16 {%0,%1,%2,%3}, [%4];" \
        : "=r"(r0), "=r"(r1), "=r"(r2), "=r"(r3) : "r"(a))

#define MMA16(d, a, b0, b1) \
    asm volatile( \
        "mma.sync.aligned.m16n8k16.row.col.f32.f16.f16.f32 " \
        "{%0,%1,%2,%3},{%4,%5,%6,%7},{%8,%9},{%0,%1,%2,%3};" \
        : "+f"((d)[0]), "+f"((d)[1]), "+f"((d)[2]), "+f"((d)[3]) \
        : "r"((a)[0]), "r"((a)[1]), "r"((a)[2]), "r"((a)[3]), "r"(b0), "r"(b1))

__device__ __forceinline__ uint32_t pk_h2(__half a, __half b) {
    __half2 t = __halves2half2(a, b);
    return *reinterpret_cast<uint32_t*>(&t);
}

// ---------------- fused router: scores + topk lists + complement + X fp16 -------
__global__ void router_kernel(const float* __restrict__ x,
                              const float* __restrict__ rw,
                              __half* __restrict__ xh) {
    int gw = (blockIdx.x * blockDim.x + threadIdx.x) >> 5;
    int lane = threadIdx.x & 31;
    if (gw >= T_TOK) return;
    const float* xr = x + (size_t)gw * DDIM;
    __half* xo = xh + (size_t)gw * DDIM;
    float acc[NEXP];
#pragma unroll
    for (int e = 0; e < NEXP; e++) acc[e] = 0.f;
    for (int d = lane; d < DDIM; d += 32) {
        float xv = xr[d];
        xo[d] = __float2half_rn(xv);
        const float4* r4 = reinterpret_cast<const float4*>(rw + (size_t)d * NEXP);
        float4 r0 = r4[0], r1 = r4[1];
        acc[0] = fmaf(xv, r0.x, acc[0]); acc[1] = fmaf(xv, r0.y, acc[1]);
        acc[2] = fmaf(xv, r0.z, acc[2]); acc[3] = fmaf(xv, r0.w, acc[3]);
        acc[4] = fmaf(xv, r1.x, acc[4]); acc[5] = fmaf(xv, r1.y, acc[5]);
        acc[6] = fmaf(xv, r1.z, acc[6]); acc[7] = fmaf(xv, r1.w, acc[7]);
    }
#pragma unroll
    for (int off = 16; off > 0; off >>= 1)
#pragma unroll
        for (int e = 0; e < NEXP; e++)
            acc[e] += __shfl_xor_sync(0xffffffffu, acc[e], off);
    if (lane == 0) {
        float m = acc[0];
#pragma unroll
        for (int e = 1; e < NEXP; e++) m = fmaxf(m, acc[e]);
        float p[NEXP], s = 0.f;
#pragma unroll
        for (int e = 0; e < NEXP; e++) { p[e] = expf(acc[e] - m); s += p[e]; }
        float inv = 1.f / s;
#pragma unroll
        for (int e = 0; e < NEXP; e++) p[e] *= inv;
#pragma unroll
        for (int e = 0; e < NEXP; e++) {
            int rank = 0;
#pragma unroll
            for (int e2 = 0; e2 < NEXP; e2++)
                rank += (p[e2] > p[e] || (p[e2] == p[e] && e2 < e)) ? 1 : 0;
            bool sel = (rank < TOPK);
            g_W[gw * NEXP + e] = sel ? p[e] : 0.f;
            if (sel) {
                int pos = atomicAdd(&g_cnt[e], 1);
                g_idx[e * IDXSTR + pos] = gw;
            } else {
                int pos = atomicAdd(&g_cntz[e], 1);
                g_idxz[e * IDXSTR + pos] = gw;
            }
        }
    }
}

// ---------------- zero only unselected (token, expert) H slots -------------------
__global__ void zeroSel() {
    const int e = blockIdx.x;
    const int nz = g_cntz[e];
    const int sub = threadIdx.x >> 6;
    const int ln  = threadIdx.x & 63;
    for (int i = blockIdx.y * 4 + sub; i < nz; i += 32 * 4) {
        const int tok = g_idxz[e * IDXSTR + i];
        *reinterpret_cast<uint4*>(g_H + (size_t)tok * KDOWN + e * FDIM + ln * 8) =
            make_uint4(0, 0, 0, 0);
    }
}

// ---------------- merged weight transpose/convert + counter reset ----------------
__device__ __forceinline__ void tpose_body(
    const float* __restrict__ src, __half* __restrict__ dst,
    int C, long long zs, long long zd, int rs) {
    __shared__ float t[32][33];
    int c0 = blockIdx.x * 32, r0 = blockIdx.y * 32;
    int tx = threadIdx.x, ty = threadIdx.y;
#pragma unroll
    for (int k = 0; k < 32; k += 8)
        t[ty + k][tx] = src[zs + (long long)(r0 + ty + k) * C + c0 + tx];
    __syncthreads();
#pragma unroll
    for (int k = 0; k < 32; k += 8) {
        float v = t[tx][ty + k];
        int n = c0 + ty + k, r = r0 + tx;
        dst[zd + (long long)n * rs + r] = __float2half_rn(v);
    }
}

__global__ void prepAll(const float* __restrict__ wg, const float* __restrict__ wu,
                        const float* __restrict__ wsg, const float* __restrict__ wsu,
                        const float* __restrict__ wd,  const float* __restrict__ wsd,
                        __half* bg, __half* bu, __half* bsg, __half* bsu, __half* bd) {
    if (blockIdx.x == 0 && blockIdx.y == 0 && blockIdx.z == 0 &&
        threadIdx.y == 0 && threadIdx.x < NEXP) {
        g_cnt[threadIdx.x] = 0;
        g_cntz[threadIdx.x] = 0;
    }
    int z = blockIdx.z;
    if (z < 8) {
        if (blockIdx.x >= 16) return;
        tpose_body(wg, bg, FDIM, (long long)z * DDIM * FDIM, (long long)z * FDIM * DDIM, DDIM);
    } else if (z < 16) {
        if (blockIdx.x >= 16) return;
        int e = z - 8;
        tpose_body(wu, bu, FDIM, (long long)e * DDIM * FDIM, (long long)e * FDIM * DDIM, DDIM);
    } else if (z == 16) {
        tpose_body(wsg, bsg, FSDIM, 0, 0, DDIM);
    } else if (z == 17) {
        tpose_body(wsu, bsu, FSDIM, 0, 0, DDIM);
    } else if (z < 26) {
        if (blockIdx.y >= 16) return;
        int e = z - 18;
        tpose_body(wd, bd, DDIM, (long long)e * FDIM * DDIM, (long long)e * FDIM, KDOWN);
    } else {
        tpose_body(wsd, bd, DDIM, 0, (long long)NEXP * FDIM, KDOWN);
    }
}

// ---------------- merged gate+up fp16 MMA GEMM ------------------------------------
// CTA tile 128m x 64n; 8 warps = 4(m) x 2(n), warp tile 32x32; 2 CTAs/SM.
// buffer: A[128m] + Bg[64n] + Bu[64n]
#define GU_SBUF (TILEB + 2 * BTILE64)   // 36864
#define GU_SMEM (2 * GU_SBUF)           // 73728

__global__ __launch_bounds__(256, 2)
void gu_mma(const __half* __restrict__ X,
            const __half* __restrict__ Gw,  const __half* __restrict__ Uw,
            const __half* __restrict__ Gsw, const __half* __restrict__ Usw) {
    const int e = blockIdx.z;
    const int bm = blockIdx.y * 128, bn = blockIdx.x * 64;

    const __half *Bg, *Bu;
    const int* tix = nullptr;
    int cnt = 0, colExp, scaled;
    if (e < NEXP) {
        cnt = g_cnt[e];
        if (bm >= ((cnt + 127) & ~127)) return;
        if (bn >= FDIM) return;
        tix = g_idx + (size_t)e * IDXSTR;
        Bg = Gw + (size_t)e * FDIM * DDIM;
        Bu = Uw + (size_t)e * FDIM * DDIM;
        colExp = e * FDIM; scaled = 1;
    } else {
        Bg = Gsw; Bu = Usw;
        colExp = NEXP * FDIM; scaled = 0;
    }

    extern __shared__ __align__(16) char smem[];
    const uint32_t sb = smem_u32(smem);
    const int tid = threadIdx.x;
    const int wid = tid >> 5, lane = tid & 31;
    const int grp = lane >> 2, tI = lane & 3;
    const int wm = (wid >> 1) * 32, wn = (wid & 1) * 32;

    // A cp.async slots (128 rows)
    const int r0 = tid >> 3, q = tid & 7;
    uint32_t dsA[4];
    size_t gA[4];
#pragma unroll
    for (int p = 0; p < 4; p++) {
        const int row = r0 + 32 * p;
        dsA[p] = row * MSTRIDE + q * 16;
        const int tokA = tix ? tix[min(bm + row, cnt - 1)] : (bm + row);
        gA[p] = (size_t)tokA * DDIM + q * 8;
    }
    // B cp.async slots (64 n-rows per tile, 2 slots each)
    const int br = tid >> 2, bq = tid & 3;
    uint32_t dsB[2];
    size_t gB[2];
#pragma unroll
    for (int p = 0; p < 2; p++) {
        dsB[p] = br * MSTRIDE + bq * 16 + p * 64;
        gB[p] = (size_t)(bn + br) * DDIM + bq * 8 + p * 32;
    }

    const uint32_t aOff = (lane & 15) * MSTRIDE + (lane >> 4) * 16;
    const uint32_t bOff = (lane & 7) * MSTRIDE + ((lane >> 3) & 1) * 16
                        + (lane >> 4) * 8 * MSTRIDE;

    float accG[2][4][4], accU[2][4][4];
#pragma unroll
    for (int i = 0; i < 2; i++)
#pragma unroll
        for (int j = 0; j < 4; j++)
#pragma unroll
            for (int r = 0; r < 4; r++) { accG[i][j][r] = 0.f; accU[i][j][r] = 0.f; }

    const int NC = DDIM / BK;   // 16

    auto issue = [&](int kc, int buf) {
        const int k0 = kc * BK;
        const uint32_t s = sb + buf * GU_SBUF;
#pragma unroll
        for (int p = 0; p < 4; p++)
            CP16(s + dsA[p], X + gA[p] + k0);
#pragma unroll
        for (int p = 0; p < 2; p++) {
            CP16(s + TILEB + dsB[p],           Bg + gB[p] + k0);
            CP16(s + TILEB + BTILE64 + dsB[p], Bu + gB[p] + k0);
        }
        CP_COMMIT();
    };

    issue(0, 0);
    for (int kc = 0; kc < NC; kc++) {
        const int buf = kc & 1;
        if (kc + 1 < NC) { issue(kc + 1, buf ^ 1); CP_WAIT1(); }
        else             { CP_WAIT0(); }
        __syncthreads();
        const uint32_t s = sb + buf * GU_SBUF;
#pragma unroll
        for (int ks = 0; ks < 4; ks++) {
            uint32_t aF[2][4];
            const uint32_t aBase = s + wm * MSTRIDE + aOff + ks * 32;
#pragma unroll
            for (int tm = 0; tm < 2; tm++)
                LDSM4(aF[tm][0], aF[tm][1], aF[tm][2], aF[tm][3],
                      aBase + tm * 16 * MSTRIDE);
            const uint32_t bgB = s + TILEB + wn * MSTRIDE + bOff + ks * 32;
            const uint32_t buB = s + TILEB + BTILE64 + wn * MSTRIDE + bOff + ks * 32;
#pragma unroll
            for (int tn2 = 0; tn2 < 2; tn2++) {
                uint32_t g[4], u[4];
                LDSM4(g[0], g[1], g[2], g[3], bgB + tn2 * 16 * MSTRIDE);
                LDSM4(u[0], u[1], u[2], u[3], buB + tn2 * 16 * MSTRIDE);
                const int tn = tn2 * 2;
#pragma unroll
                for (int tm = 0; tm < 2; tm++) MMA16(accG[tm][tn],     aF[tm], g[0], g[1]);
#pragma unroll
                for (int tm = 0; tm < 2; tm++) MMA16(accU[tm][tn],     aF[tm], u[0], u[1]);
#pragma unroll
                for (int tm = 0; tm < 2; tm++) MMA16(accG[tm][tn + 1], aF[tm], g[2], g[3]);
#pragma unroll
                for (int tm = 0; tm < 2; tm++) MMA16(accU[tm][tn + 1], aF[tm], u[2], u[3]);
            }
        }
        __syncthreads();
    }

    const int colbase = colExp + bn + wn;
#pragma unroll
    for (int tm = 0; tm < 2; tm++) {
#pragma unroll
        for (int half = 0; half < 2; half++) {
            const int i = bm + wm + tm * 16 + grp + half * 8;
            const int token = tix ? tix[min(i, cnt - 1)] : i;
            const float wgt = scaled ? g_W[token * NEXP + e] : 1.0f;
            const size_t rowoff = (size_t)token * KDOWN;
#pragma unroll
            for (int tn = 0; tn < 4; tn++) {
                float gv0 = accG[tm][tn][half * 2 + 0];
                float gv1 = accG[tm][tn][half * 2 + 1];
                float uv0 = accU[tm][tn][half * 2 + 0];
                float uv1 = accU[tm][tn][half * 2 + 1];
                float h0 = gv0 / (1.f + expf(-gv0)) * uv0 * wgt;
                float h1 = gv1 / (1.f + expf(-gv1)) * uv1 * wgt;
                const int col = colbase + tn * 8 + tI * 2;
                *reinterpret_cast<uint32_t*>(g_H + rowoff + col) =
                    pk_h2(__float2half_rn(h0), __float2half_rn(h1));
            }
        }
    }
}

// ---------------- down fp16 MMA GEMM (combine) --------------------------------------
#define DN_SBUF (2 * TILEB)       // 36864
#define DN_SMEM (2 * DN_SBUF)     // 73728

__global__ __launch_bounds__(256, 2)
void dn_mma(float* __restrict__ out) {
    extern __shared__ __align__(16) char smem[];
    const uint32_t sb = smem_u32(smem);
    const int tid = threadIdx.x;
    const int wid = tid >> 5, lane = tid & 31;
    const int grp = lane >> 2, tI = lane & 3;
    const int wm = (wid >> 2) * 64, wn = (wid & 3) * 32;
    const int bm = blockIdx.y * 128, bn = blockIdx.x * 128;

    const int r0 = tid >> 3, q = tid & 7;
    uint32_t ds[4];
    size_t gA[4], gB[4];
#pragma unroll
    for (int p = 0; p < 4; p++) {
        const int row = r0 + 32 * p;
        ds[p] = row * MSTRIDE + q * 16;
        gA[p] = (size_t)(bm + row) * KDOWN + q * 8;
        gB[p] = (size_t)(bn + row) * KDOWN + q * 8;
    }

    const uint32_t aOff = (lane & 15) * MSTRIDE + (lane >> 4) * 16;
    const uint32_t bOff = (lane & 7) * MSTRIDE + ((lane >> 3) & 1) * 16
                        + (lane >> 4) * 8 * MSTRIDE;

    float acc[4][4][4];
#pragma unroll
    for (int i = 0; i < 4; i++)
#pragma unroll
        for (int j = 0; j < 4; j++)
#pragma unroll
            for (int r = 0; r < 4; r++) acc[i][j][r] = 0.f;

    const int NC = KDOWN / BK;   // 80

    auto issue = [&](int kc, int buf) {
        const int k0 = kc * BK;
        const uint32_t s = sb + buf * DN_SBUF;
#pragma unroll
        for (int p = 0; p < 4; p++) {
            CP16(s + ds[p],         g_H  + gA[p] + k0);
            CP16(s + TILEB + ds[p], g_Bd + gB[p] + k0);
        }
        CP_COMMIT();
    };

    issue(0, 0);
    for (int kc = 0; kc < NC; kc++) {
        const int buf = kc & 1;
        if (kc + 1 < NC) { issue(kc + 1, buf ^ 1); CP_WAIT1(); }
        else             { CP_WAIT0(); }
        __syncthreads();
        const uint32_t s = sb + buf * DN_SBUF;
#pragma unroll
        for (int ks = 0; ks < 4; ks++) {
            uint32_t aF[4][4];
            const uint32_t aBase = s + wm * MSTRIDE + aOff + ks * 32;
#pragma unroll
            for (int tm = 0; tm < 4; tm++)
                LDSM4(aF[tm][0], aF[tm][1], aF[tm][2], aF[tm][3],
                      aBase + tm * 16 * MSTRIDE);
            const uint32_t bB = s + TILEB + wn * MSTRIDE + bOff + ks * 32;
#pragma unroll
            for (int tn2 = 0; tn2 < 2; tn2++) {
                uint32_t b[4];
                LDSM4(b[0], b[1], b[2], b[3], bB + tn2 * 16 * MSTRIDE);
                const int tn = tn2 * 2;
#pragma unroll
                for (int tm = 0; tm < 4; tm++) MMA16(acc[tm][tn],     aF[tm], b[0], b[1]);
#pragma unroll
                for (int tm = 0; tm < 4; tm++) MMA16(acc[tm][tn + 1], aF[tm], b[2], b[3]);
            }
        }
        __syncthreads();
    }

#pragma unroll
    for (int tm = 0; tm < 4; tm++) {
#pragma unroll
        for (int half = 0; half < 2; half++) {
            const int token = bm + wm + tm * 16 + grp + half * 8;
#pragma unroll
            for (int tn = 0; tn < 4; tn++) {
                const int col = bn + wn + tn * 8 + tI * 2;
                float2 v = make_float2(acc[tm][tn][half * 2], acc[tm][tn][half * 2 + 1]);
                *reinterpret_cast<float2*>(out + (size_t)token * DDIM + col) = v;
            }
        }
    }
}

// ---------------- launch ------------------------------------------------------------
extern "C" void kernel_launch(void* const* d_in, const int* in_sizes, int n_in,
                              void* d_out, int out_size) {
    const float* x   = (const float*)d_in[0];
    const float* rw  = (const float*)d_in[1];
    const float* wg  = (const float*)d_in[2];
    const float* wu  = (const float*)d_in[3];
    const float* wd  = (const float*)d_in[4];
    const float* wsg = (const float*)d_in[5];
    const float* wsu = (const float*)d_in[6];
    const float* wsd = (const float*)d_in[7];
    float* out = (float*)d_out;

    void *pX, *pBg, *pBu, *pBsg, *pBsu, *pBd;
    cudaGetSymbolAddress(&pX, g_X);
    cudaGetSymbolAddress(&pBg, g_Bg);   cudaGetSymbolAddress(&pBu, g_Bu);
    cudaGetSymbolAddress(&pBsg, g_Bsg); cudaGetSymbolAddress(&pBsu, g_Bsu);
    cudaGetSymbolAddress(&pBd, g_Bd);

    cudaFuncSetAttribute(gu_mma, cudaFuncAttributeMaxDynamicSharedMemorySize, GU_SMEM);
    cudaFuncSetAttribute(dn_mma, cudaFuncAttributeMaxDynamicSharedMemorySize, DN_SMEM);

    // 1: merged weight transpose/convert + embedded counter reset
    dim3 tb(32, 8);
    prepAll<<<dim3(32, 32, 27), tb>>>(wg, wu, wsg, wsu, wd, wsd,
        (__half*)pBg, (__half*)pBu, (__half*)pBsg, (__half*)pBsu, (__half*)pBd);
    // 2: fused router (scores + topk + complement lists + X fp16)
    router_kernel<<<T_TOK / 4, 128>>>(x, rw, (__half*)pX);
    // 3: zero only unselected (token, expert) H slots
    zeroSel<<<dim3(NEXP, 32), 256>>>();
    // 4: merged gate+up, 64-wide N tiles (routed z=0..7 gathered, z=8 shared)
    gu_mma<<<dim3(FSDIM / 64, T_TOK / 128, NEXP + 1), 256, GU_SMEM>>>(
        (const __half*)pX,
        (const __half*)pBg,  (const __half*)pBu,
        (const __half*)pBsg, (const __half*)pBsu);
    // 5: down + weighted combine + shared add
    dn_mma<<<dim3(DDIM / 128, T_TOK / 128), 256, DN_SMEM>>>(out);
}

// round 15
// speedup vs baseline: 1.1033x; 1.0135x over previous
#include <cuda_runtime.h>
#include <cuda_fp16.h>
#include <math.h>
#include <stdint.h>

#define T_TOK 4096
#define DDIM  1024
#define NEXP  8
#define FDIM  512
#define FSDIM 1024
#define KDOWN 5120
#define TOPK  6

#define BK 64
#define MSTRIDE 144                // 128 data + 16 pad: 16B-aligned, ldmatrix conflict-free
#define TILEB (128 * MSTRIDE)      // 18432 bytes per 128-row tile
#define BTILE64 (64 * MSTRIDE)     // 9216 bytes per 64-row tile
#define IDXSTR 4096

// ---------------- scratch ----------------------------------------------------
__device__ float g_W[T_TOK * NEXP];
__device__ int   g_idx[NEXP * IDXSTR];
__device__ int   g_idxz[NEXP * IDXSTR];
__device__ int   g_cnt[NEXP];
__device__ int   g_cntz[NEXP];
__device__ __half g_X[T_TOK * DDIM];
__device__ __half g_Bg[NEXP * FDIM * DDIM];      // fp16 weights, K-major [n][k]
__device__ __half g_Bu[NEXP * FDIM * DDIM];
__device__ __half g_Bsg[FSDIM * DDIM];
__device__ __half g_Bsu[FSDIM * DDIM];
__device__ __half g_Bd[DDIM * KDOWN];            // [n=1024][k=5120]
__device__ __half g_H[(size_t)T_TOK * KDOWN];

// ---------------- helpers ----------------------------------------------------
__device__ __forceinline__ uint32_t smem_u32(const void* p) {
    uint32_t a;
    asm("{ .reg .u64 t; cvta.to.shared.u64 t, %1; cvt.u32.u64 %0, t; }"
        : "=r"(a) : "l"(p));
    return a;
}

#define CP16(dst, src) \
    asm volatile("cp.async.cg.shared.global [%0], [%1], 16;" :: "r"(dst), "l"(src) : "memory")
#define CP_COMMIT() asm volatile("cp.async.commit_group;" ::: "memory")
#define CP_WAIT1()  asm volatile("cp.async.wait_group 1;" ::: "memory")
#define CP_WAIT0()  asm volatile("cp.async.wait_group 0;" ::: "memory")

#define LDSM4(r0, r1, r2, r3, a) \
    asm volatile("ldmatrix.sync.aligned.m8n8.x4.shared.b16 {%0,%1,%2,%3}, [%4];" \
        : "=r"(r0), "=r"(r1), "=r"(r2), "=r"(r3) : "r"(a))

#define MMA16(d, a, b0, b1) \
    asm volatile( \
        "mma.sync.aligned.m16n8k16.row.col.f32.f16.f16.f32 " \
        "{%0,%1,%2,%3},{%4,%5,%6,%7},{%8,%9},{%0,%1,%2,%3};" \
        : "+f"((d)[0]), "+f"((d)[1]), "+f"((d)[2]), "+f"((d)[3]) \
        : "r"((a)[0]), "r"((a)[1]), "r"((a)[2]), "r"((a)[3]), "r"(b0), "r"(b1))

__device__ __forceinline__ uint32_t pk_h2(__half a, __half b) {
    __half2 t = __halves2half2(a, b);
    return *reinterpret_cast<uint32_t*>(&t);
}

// ---------------- fused router: scores + topk lists + complement + X fp16 -------
__global__ void router_kernel(const float* __restrict__ x,
                              const float* __restrict__ rw,
                              __half* __restrict__ xh) {
    int gw = (blockIdx.x * blockDim.x + threadIdx.x) >> 5;
    int lane = threadIdx.x & 31;
    if (gw >= T_TOK) return;
    const float* xr = x + (size_t)gw * DDIM;
    __half* xo = xh + (size_t)gw * DDIM;
    float acc[NEXP];
#pragma unroll
    for (int e = 0; e < NEXP; e++) acc[e] = 0.f;
    for (int d = lane; d < DDIM; d += 32) {
        float xv = xr[d];
        xo[d] = __float2half_rn(xv);
        const float4* r4 = reinterpret_cast<const float4*>(rw + (size_t)d * NEXP);
        float4 r0 = r4[0], r1 = r4[1];
        acc[0] = fmaf(xv, r0.x, acc[0]); acc[1] = fmaf(xv, r0.y, acc[1]);
        acc[2] = fmaf(xv, r0.z, acc[2]); acc[3] = fmaf(xv, r0.w, acc[3]);
        acc[4] = fmaf(xv, r1.x, acc[4]); acc[5] = fmaf(xv, r1.y, acc[5]);
        acc[6] = fmaf(xv, r1.z, acc[6]); acc[7] = fmaf(xv, r1.w, acc[7]);
    }
#pragma unroll
    for (int off = 16; off > 0; off >>= 1)
#pragma unroll
        for (int e = 0; e < NEXP; e++)
            acc[e] += __shfl_xor_sync(0xffffffffu, acc[e], off);
    if (lane == 0) {
        float m = acc[0];
#pragma unroll
        for (int e = 1; e < NEXP; e++) m = fmaxf(m, acc[e]);
        float p[NEXP], s = 0.f;
#pragma unroll
        for (int e = 0; e < NEXP; e++) { p[e] = expf(acc[e] - m); s += p[e]; }
        float inv = 1.f / s;
#pragma unroll
        for (int e = 0; e < NEXP; e++) p[e] *= inv;
#pragma unroll
        for (int e = 0; e < NEXP; e++) {
            int rank = 0;
#pragma unroll
            for (int e2 = 0; e2 < NEXP; e2++)
                rank += (p[e2] > p[e] || (p[e2] == p[e] && e2 < e)) ? 1 : 0;
            bool sel = (rank < TOPK);
            g_W[gw * NEXP + e] = sel ? p[e] : 0.f;
            if (sel) {
                int pos = atomicAdd(&g_cnt[e], 1);
                g_idx[e * IDXSTR + pos] = gw;
            } else {
                int pos = atomicAdd(&g_cntz[e], 1);
                g_idxz[e * IDXSTR + pos] = gw;
            }
        }
    }
}

// ---------------- zero only unselected (token, expert) H slots -------------------
__global__ void zeroSel() {
    const int e = blockIdx.x;
    const int nz = g_cntz[e];
    const int sub = threadIdx.x >> 6;
    const int ln  = threadIdx.x & 63;
    for (int i = blockIdx.y * 4 + sub; i < nz; i += 32 * 4) {
        const int tok = g_idxz[e * IDXSTR + i];
        *reinterpret_cast<uint4*>(g_H + (size_t)tok * KDOWN + e * FDIM + ln * 8) =
            make_uint4(0, 0, 0, 0);
    }
}

// ---------------- merged weight transpose/convert + counter reset ----------------
// 64(r) x 32(n) tiles: coalesced 128B reads AND 16B/thread coalesced writes.
__device__ __forceinline__ void tpose_body(
    const float* __restrict__ src, __half* __restrict__ dst,
    int C, long long zs, long long zd, int rs) {
    __shared__ float t[64][33];
    int c0 = blockIdx.x * 32, r0 = blockIdx.y * 64;
    int tx = threadIdx.x, ty = threadIdx.y;   // block (32, 8)
#pragma unroll
    for (int k = 0; k < 64; k += 8)
        t[ty + k][tx] = src[zs + (long long)(r0 + ty + k) * C + c0 + tx];
    __syncthreads();
    const int tid = ty * 32 + tx;
    const int n = tid >> 3;            // 0..31  output n-row
    const int rc = (tid & 7) * 8;      // 0..56  r-chunk of 8
    __half h[8];
#pragma unroll
    for (int j = 0; j < 8; j++)
        h[j] = __float2half_rn(t[rc + j][n]);
    *reinterpret_cast<uint4*>(dst + zd + (long long)(c0 + n) * rs + r0 + rc) =
        *reinterpret_cast<uint4*>(h);
}

// z 0..7: w_gate e | z 8..15: w_up e | z 16: ws_gate | z 17: ws_up
// z 18..25: w_down e (y<8) | z 26: ws_down.  grid(32, 16, 27), block(32, 8)
__global__ void prepAll(const float* __restrict__ wg, const float* __restrict__ wu,
                        const float* __restrict__ wsg, const float* __restrict__ wsu,
                        const float* __restrict__ wd,  const float* __restrict__ wsd,
                        __half* bg, __half* bu, __half* bsg, __half* bsu, __half* bd) {
    if (blockIdx.x == 0 && blockIdx.y == 0 && blockIdx.z == 0 &&
        threadIdx.y == 0 && threadIdx.x < NEXP) {
        g_cnt[threadIdx.x] = 0;
        g_cntz[threadIdx.x] = 0;
    }
    int z = blockIdx.z;
    if (z < 8) {
        if (blockIdx.x >= 16) return;     // w_gate cols = FDIM
        tpose_body(wg, bg, FDIM, (long long)z * DDIM * FDIM, (long long)z * FDIM * DDIM, DDIM);
    } else if (z < 16) {
        if (blockIdx.x >= 16) return;
        int e = z - 8;
        tpose_body(wu, bu, FDIM, (long long)e * DDIM * FDIM, (long long)e * FDIM * DDIM, DDIM);
    } else if (z == 16) {
        tpose_body(wsg, bsg, FSDIM, 0, 0, DDIM);
    } else if (z == 17) {
        tpose_body(wsu, bsu, FSDIM, 0, 0, DDIM);
    } else if (z < 26) {
        if (blockIdx.y >= 8) return;      // w_down rows = FDIM -> 8 r-tiles of 64
        int e = z - 18;
        tpose_body(wd, bd, DDIM, (long long)e * FDIM * DDIM, (long long)e * FDIM, KDOWN);
    } else {
        tpose_body(wsd, bd, DDIM, 0, (long long)NEXP * FDIM, KDOWN);
    }
}

// ---------------- merged gate+up fp16 MMA GEMM ------------------------------------
// CTA tile 128m x 64n; 8 warps = 4(m) x 2(n), warp tile 32x32; 2 CTAs/SM.
#define GU_SBUF (TILEB + 2 * BTILE64)   // 36864
#define GU_SMEM (2 * GU_SBUF)           // 73728

__global__ __launch_bounds__(256, 2)
void gu_mma(const __half* __restrict__ X,
            const __half* __restrict__ Gw,  const __half* __restrict__ Uw,
            const __half* __restrict__ Gsw, const __half* __restrict__ Usw) {
    const int e = blockIdx.z;
    const int bm = blockIdx.y * 128, bn = blockIdx.x * 64;

    const __half *Bg, *Bu;
    const int* tix = nullptr;
    int cnt = 0, colExp, scaled;
    if (e < NEXP) {
        cnt = g_cnt[e];
        if (bm >= ((cnt + 127) & ~127)) return;
        if (bn >= FDIM) return;
        tix = g_idx + (size_t)e * IDXSTR;
        Bg = Gw + (size_t)e * FDIM * DDIM;
        Bu = Uw + (size_t)e * FDIM * DDIM;
        colExp = e * FDIM; scaled = 1;
    } else {
        Bg = Gsw; Bu = Usw;
        colExp = NEXP * FDIM; scaled = 0;
    }

    extern __shared__ __align__(16) char smem[];
    const uint32_t sb = smem_u32(smem);
    const int tid = threadIdx.x;
    const int wid = tid >> 5, lane = tid & 31;
    const int grp = lane >> 2, tI = lane & 3;
    const int wm = (wid >> 1) * 32, wn = (wid & 1) * 32;

    const int r0 = tid >> 3, q = tid & 7;
    uint32_t dsA[4];
    size_t gA[4];
#pragma unroll
    for (int p = 0; p < 4; p++) {
        const int row = r0 + 32 * p;
        dsA[p] = row * MSTRIDE + q * 16;
        const int tokA = tix ? tix[min(bm + row, cnt - 1)] : (bm + row);
        gA[p] = (size_t)tokA * DDIM + q * 8;
    }
    const int br = tid >> 2, bq = tid & 3;
    uint32_t dsB[2];
    size_t gB[2];
#pragma unroll
    for (int p = 0; p < 2; p++) {
        dsB[p] = br * MSTRIDE + bq * 16 + p * 64;
        gB[p] = (size_t)(bn + br) * DDIM + bq * 8 + p * 32;
    }

    const uint32_t aOff = (lane & 15) * MSTRIDE + (lane >> 4) * 16;
    const uint32_t bOff = (lane & 7) * MSTRIDE + ((lane >> 3) & 1) * 16
                        + (lane >> 4) * 8 * MSTRIDE;

    float accG[2][4][4], accU[2][4][4];
#pragma unroll
    for (int i = 0; i < 2; i++)
#pragma unroll
        for (int j = 0; j < 4; j++)
#pragma unroll
            for (int r = 0; r < 4; r++) { accG[i][j][r] = 0.f; accU[i][j][r] = 0.f; }

    const int NC = DDIM / BK;   // 16

    auto issue = [&](int kc, int buf) {
        const int k0 = kc * BK;
        const uint32_t s = sb + buf * GU_SBUF;
#pragma unroll
        for (int p = 0; p < 4; p++)
            CP16(s + dsA[p], X + gA[p] + k0);
#pragma unroll
        for (int p = 0; p < 2; p++) {
            CP16(s + TILEB + dsB[p],           Bg + gB[p] + k0);
            CP16(s + TILEB + BTILE64 + dsB[p], Bu + gB[p] + k0);
        }
        CP_COMMIT();
    };

    issue(0, 0);
    for (int kc = 0; kc < NC; kc++) {
        const int buf = kc & 1;
        if (kc + 1 < NC) { issue(kc + 1, buf ^ 1); CP_WAIT1(); }
        else             { CP_WAIT0(); }
        __syncthreads();
        const uint32_t s = sb + buf * GU_SBUF;
#pragma unroll
        for (int ks = 0; ks < 4; ks++) {
            uint32_t aF[2][4];
            const uint32_t aBase = s + wm * MSTRIDE + aOff + ks * 32;
#pragma unroll
            for (int tm = 0; tm < 2; tm++)
                LDSM4(aF[tm][0], aF[tm][1], aF[tm][2], aF[tm][3],
                      aBase + tm * 16 * MSTRIDE);
            const uint32_t bgB = s + TILEB + wn * MSTRIDE + bOff + ks * 32;
            const uint32_t buB = s + TILEB + BTILE64 + wn * MSTRIDE + bOff + ks * 32;
#pragma unroll
            for (int tn2 = 0; tn2 < 2; tn2++) {
                uint32_t g[4], u[4];
                LDSM4(g[0], g[1], g[2], g[3], bgB + tn2 * 16 * MSTRIDE);
                LDSM4(u[0], u[1], u[2], u[3], buB + tn2 * 16 * MSTRIDE);
                const int tn = tn2 * 2;
#pragma unroll
                for (int tm = 0; tm < 2; tm++) MMA16(accG[tm][tn],     aF[tm], g[0], g[1]);
#pragma unroll
                for (int tm = 0; tm < 2; tm++) MMA16(accU[tm][tn],     aF[tm], u[0], u[1]);
#pragma unroll
                for (int tm = 0; tm < 2; tm++) MMA16(accG[tm][tn + 1], aF[tm], g[2], g[3]);
#pragma unroll
                for (int tm = 0; tm < 2; tm++) MMA16(accU[tm][tn + 1], aF[tm], u[2], u[3]);
            }
        }
        __syncthreads();
    }

    const int colbase = colExp + bn + wn;
#pragma unroll
    for (int tm = 0; tm < 2; tm++) {
#pragma unroll
        for (int half = 0; half < 2; half++) {
            const int i = bm + wm + tm * 16 + grp + half * 8;
            const int token = tix ? tix[min(i, cnt - 1)] : i;
            const float wgt = scaled ? g_W[token * NEXP + e] : 1.0f;
            const size_t rowoff = (size_t)token * KDOWN;
#pragma unroll
            for (int tn = 0; tn < 4; tn++) {
                float gv0 = accG[tm][tn][half * 2 + 0];
                float gv1 = accG[tm][tn][half * 2 + 1];
                float uv0 = accU[tm][tn][half * 2 + 0];
                float uv1 = accU[tm][tn][half * 2 + 1];
                float h0 = gv0 / (1.f + expf(-gv0)) * uv0 * wgt;
                float h1 = gv1 / (1.f + expf(-gv1)) * uv1 * wgt;
                const int col = colbase + tn * 8 + tI * 2;
                *reinterpret_cast<uint32_t*>(g_H + rowoff + col) =
                    pk_h2(__float2half_rn(h0), __float2half_rn(h1));
            }
        }
    }
}

// ---------------- down fp16 MMA GEMM (combine) --------------------------------------
#define DN_SBUF (2 * TILEB)       // 36864
#define DN_SMEM (2 * DN_SBUF)     // 73728

__global__ __launch_bounds__(256, 2)
void dn_mma(float* __restrict__ out) {
    extern __shared__ __align__(16) char smem[];
    const uint32_t sb = smem_u32(smem);
    const int tid = threadIdx.x;
    const int wid = tid >> 5, lane = tid & 31;
    const int grp = lane >> 2, tI = lane & 3;
    const int wm = (wid >> 2) * 64, wn = (wid & 3) * 32;
    const int bm = blockIdx.y * 128, bn = blockIdx.x * 128;

    const int r0 = tid >> 3, q = tid & 7;
    uint32_t ds[4];
    size_t gA[4], gB[4];
#pragma unroll
    for (int p = 0; p < 4; p++) {
        const int row = r0 + 32 * p;
        ds[p] = row * MSTRIDE + q * 16;
        gA[p] = (size_t)(bm + row) * KDOWN + q * 8;
        gB[p] = (size_t)(bn + row) * KDOWN + q * 8;
    }

    const uint32_t aOff = (lane & 15) * MSTRIDE + (lane >> 4) * 16;
    const uint32_t bOff = (lane & 7) * MSTRIDE + ((lane >> 3) & 1) * 16
                        + (lane >> 4) * 8 * MSTRIDE;

    float acc[4][4][4];
#pragma unroll
    for (int i = 0; i < 4; i++)
#pragma unroll
        for (int j = 0; j < 4; j++)
#pragma unroll
            for (int r = 0; r < 4; r++) acc[i][j][r] = 0.f;

    const int NC = KDOWN / BK;   // 80

    auto issue = [&](int kc, int buf) {
        const int k0 = kc * BK;
        const uint32_t s = sb + buf * DN_SBUF;
#pragma unroll
        for (int p = 0; p < 4; p++) {
            CP16(s + ds[p],         g_H  + gA[p] + k0);
            CP16(s + TILEB + ds[p], g_Bd + gB[p] + k0);
        }
        CP_COMMIT();
    };

    issue(0, 0);
    for (int kc = 0; kc < NC; kc++) {
        const int buf = kc & 1;
        if (kc + 1 < NC) { issue(kc + 1, buf ^ 1); CP_WAIT1(); }
        else             { CP_WAIT0(); }
        __syncthreads();
        const uint32_t s = sb + buf * DN_SBUF;
#pragma unroll
        for (int ks = 0; ks < 4; ks++) {
            uint32_t aF[4][4];
            const uint32_t aBase = s + wm * MSTRIDE + aOff + ks * 32;
#pragma unroll
            for (int tm = 0; tm < 4; tm++)
                LDSM4(aF[tm][0], aF[tm][1], aF[tm][2], aF[tm][3],
                      aBase + tm * 16 * MSTRIDE);
            const uint32_t bB = s + TILEB + wn * MSTRIDE + bOff + ks * 32;
#pragma unroll
            for (int tn2 = 0; tn2 < 2; tn2++) {
                uint32_t b[4];
                LDSM4(b[0], b[1], b[2], b[3], bB + tn2 * 16 * MSTRIDE);
                const int tn = tn2 * 2;
#pragma unroll
                for (int tm = 0; tm < 4; tm++) MMA16(acc[tm][tn],     aF[tm], b[0], b[1]);
#pragma unroll
                for (int tm = 0; tm < 4; tm++) MMA16(acc[tm][tn + 1], aF[tm], b[2], b[3]);
            }
        }
        __syncthreads();
    }

#pragma unroll
    for (int tm = 0; tm < 4; tm++) {
#pragma unroll
        for (int half = 0; half < 2; half++) {
            const int token = bm + wm + tm * 16 + grp + half * 8;
#pragma unroll
            for (int tn = 0; tn < 4; tn++) {
                const int col = bn + wn + tn * 8 + tI * 2;
                float2 v = make_float2(acc[tm][tn][half * 2], acc[tm][tn][half * 2 + 1]);
                *reinterpret_cast<float2*>(out + (size_t)token * DDIM + col) = v;
            }
        }
    }
}

// ---------------- launch ------------------------------------------------------------
extern "C" void kernel_launch(void* const* d_in, const int* in_sizes, int n_in,
                              void* d_out, int out_size) {
    const float* x   = (const float*)d_in[0];
    const float* rw  = (const float*)d_in[1];
    const float* wg  = (const float*)d_in[2];
    const float* wu  = (const float*)d_in[3];
    const float* wd  = (const float*)d_in[4];
    const float* wsg = (const float*)d_in[5];
    const float* wsu = (const float*)d_in[6];
    const float* wsd = (const float*)d_in[7];
    float* out = (float*)d_out;

    void *pX, *pBg, *pBu, *pBsg, *pBsu, *pBd;
    cudaGetSymbolAddress(&pX, g_X);
    cudaGetSymbolAddress(&pBg, g_Bg);   cudaGetSymbolAddress(&pBu, g_Bu);
    cudaGetSymbolAddress(&pBsg, g_Bsg); cudaGetSymbolAddress(&pBsu, g_Bsu);
    cudaGetSymbolAddress(&pBd, g_Bd);

    cudaFuncSetAttribute(gu_mma, cudaFuncAttributeMaxDynamicSharedMemorySize, GU_SMEM);
    cudaFuncSetAttribute(dn_mma, cudaFuncAttributeMaxDynamicSharedMemorySize, DN_SMEM);

    // 1: merged weight transpose/convert (coalesced 64-wide writes) + counter reset
    dim3 tb(32, 8);
    prepAll<<<dim3(32, 16, 27), tb>>>(wg, wu, wsg, wsu, wd, wsd,
        (__half*)pBg, (__half*)pBu, (__half*)pBsg, (__half*)pBsu, (__half*)pBd);
    // 2: fused router (scores + topk + complement lists + X fp16)
    router_kernel<<<T_TOK / 4, 128>>>(x, rw, (__half*)pX);
    // 3: zero only unselected (token, expert) H slots
    zeroSel<<<dim3(NEXP, 32), 256>>>();
    // 4: merged gate+up, 64-wide N tiles (routed z=0..7 gathered, z=8 shared)
    gu_mma<<<dim3(FSDIM / 64, T_TOK / 128, NEXP + 1), 256, GU_SMEM>>>(
        (const __half*)pX,
        (const __half*)pBg,  (const __half*)pBu,
        (const __half*)pBsg, (const __half*)pBsu);
    // 5: down + weighted combine + shared add
    dn_mma<<<dim3(DDIM / 128, T_TOK / 128), 256, DN_SMEM>>>(out);
}